// round 3
// baseline (speedup 1.0000x reference)
#include <cuda_runtime.h>

// out[b,s,t] = sum_d input[b,t,s,d] * affine[d,t]
// B=8, T=128, S=256, D=1024, fp32.
// input : d_in[0], row (b,t,s,:) contiguous (4KB)
// affine: d_in[1], affine[d*T + t]
// out   : [B,S,T]

#define B_ 8
#define T_ 128
#define S_ 256
#define D_ 1024
#define D4 (D_ / 4)   // 256 float4 per row

__global__ __launch_bounds__(256)
void filtersum_kernel(const float* __restrict__ in,
                      const float* __restrict__ affine,
                      float* __restrict__ out) {
    __shared__ float aff_s[D_];

    const int bt = blockIdx.x;          // 0..B_*T_-1
    const int b  = bt / T_;
    const int t  = bt % T_;
    const int tid  = threadIdx.x;
    const int lane = tid & 31;
    const int w    = tid >> 5;          // warp id, 0..7

    // Cooperative load of affine column t into shared (strided gather, L2-hot).
    #pragma unroll
    for (int d = tid; d < D_; d += 256)
        aff_s[d] = affine[d * T_ + t];
    __syncthreads();

    // Per-lane affine chunks in registers: lane holds float4 at indices lane + 32*c.
    float4 aff[8];
    const float4* affs4 = reinterpret_cast<const float4*>(aff_s);
    #pragma unroll
    for (int c = 0; c < 8; c++)
        aff[c] = affs4[lane + 32 * c];

    const float4* base = reinterpret_cast<const float4*>(in)
                       + (size_t)(b * T_ + t) * S_ * D4;

    const int s0 = w * 32;              // each warp owns 32 consecutive s values

    #pragma unroll 1
    for (int j = 0; j < 32; j += 4) {
        const float4* r0 = base + (size_t)(s0 + j) * D4;
        const float4* r1 = r0 + D4;
        const float4* r2 = r1 + D4;
        const float4* r3 = r2 + D4;

        float acc0 = 0.0f, acc1 = 0.0f, acc2 = 0.0f, acc3 = 0.0f;
        #pragma unroll
        for (int c = 0; c < 8; c++) {
            float4 v0 = r0[lane + 32 * c];
            float4 v1 = r1[lane + 32 * c];
            float4 v2 = r2[lane + 32 * c];
            float4 v3 = r3[lane + 32 * c];
            acc0 = fmaf(v0.x, aff[c].x, acc0);
            acc0 = fmaf(v0.y, aff[c].y, acc0);
            acc0 = fmaf(v0.z, aff[c].z, acc0);
            acc0 = fmaf(v0.w, aff[c].w, acc0);
            acc1 = fmaf(v1.x, aff[c].x, acc1);
            acc1 = fmaf(v1.y, aff[c].y, acc1);
            acc1 = fmaf(v1.z, aff[c].z, acc1);
            acc1 = fmaf(v1.w, aff[c].w, acc1);
            acc2 = fmaf(v2.x, aff[c].x, acc2);
            acc2 = fmaf(v2.y, aff[c].y, acc2);
            acc2 = fmaf(v2.z, aff[c].z, acc2);
            acc2 = fmaf(v2.w, aff[c].w, acc2);
            acc3 = fmaf(v3.x, aff[c].x, acc3);
            acc3 = fmaf(v3.y, aff[c].y, acc3);
            acc3 = fmaf(v3.z, aff[c].z, acc3);
            acc3 = fmaf(v3.w, aff[c].w, acc3);
        }

        // warp reductions
        #pragma unroll
        for (int off = 16; off > 0; off >>= 1) {
            acc0 += __shfl_xor_sync(0xFFFFFFFFu, acc0, off);
            acc1 += __shfl_xor_sync(0xFFFFFFFFu, acc1, off);
            acc2 += __shfl_xor_sync(0xFFFFFFFFu, acc2, off);
            acc3 += __shfl_xor_sync(0xFFFFFFFFu, acc3, off);
        }

        if (lane == 0) {
            float* o = out + ((size_t)b * S_ + (s0 + j)) * T_ + t;
            o[0 * T_] = acc0;
            o[1 * T_] = acc1;
            o[2 * T_] = acc2;
            o[3 * T_] = acc3;
        }
    }
}

extern "C" void kernel_launch(void* const* d_in, const int* in_sizes, int n_in,
                              void* d_out, int out_size) {
    const float* in     = (const float*)d_in[0];
    const float* affine = (const float*)d_in[1];
    float* out          = (float*)d_out;
    (void)in_sizes; (void)n_in; (void)out_size;

    dim3 grid(B_ * T_);
    dim3 block(256);
    filtersum_kernel<<<grid, block>>>(in, affine, out);
}

// round 4
// speedup vs baseline: 1.0606x; 1.0606x over previous
#include <cuda_runtime.h>

// out[b,s,t] = sum_d input[b,t,s,d] * affine[d,t]
// B=8, T=128, S=256, D=1024, fp32.
// input : d_in[0], row (b,t,s,:) contiguous (4KB)
// affine: d_in[1], affine[d*T + t]
// out   : [B,S,T]

#define B_ 8
#define T_ 128
#define S_ 256
#define D_ 1024
#define D4 (D_ / 4)    // 256 float4 per row
#define SC 128         // s rows per block (split = 2)

__global__ __launch_bounds__(256)
void filtersum_kernel(const float* __restrict__ in,
                      const float* __restrict__ affine,
                      float* __restrict__ out) {
    __shared__ float aff_s[D_];

    const int blk = blockIdx.x;         // 0 .. B_*T_*2 - 1
    const int bt  = blk >> 1;           // (b,t) pair
    const int sc  = blk & 1;            // s half
    const int b   = bt / T_;
    const int t   = bt % T_;
    const int tid  = threadIdx.x;
    const int lane = tid & 31;
    const int w    = tid >> 5;          // warp id, 0..7

    // Cooperative load of affine column t into shared (strided gather, L2-hot).
    #pragma unroll
    for (int d = tid; d < D_; d += 256)
        aff_s[d] = affine[d * T_ + t];
    __syncthreads();

    // Per-lane affine chunks in registers: lane holds float4 at indices lane + 32*c.
    float4 aff[8];
    const float4* affs4 = reinterpret_cast<const float4*>(aff_s);
    #pragma unroll
    for (int c = 0; c < 8; c++)
        aff[c] = affs4[lane + 32 * c];

    const float4* base = reinterpret_cast<const float4*>(in)
                       + (size_t)(b * T_ + t) * S_ * D4;

    const int s0 = sc * SC + w * (SC / 8);   // each warp: 16 consecutive s rows

    #pragma unroll 1
    for (int j = 0; j < SC / 8; j += 2) {
        const float4* r0 = base + (size_t)(s0 + j) * D4;
        const float4* r1 = r0 + D4;

        float acc0 = 0.0f, acc1 = 0.0f;
        #pragma unroll
        for (int c = 0; c < 8; c++) {
            float4 v0 = r0[lane + 32 * c];
            float4 v1 = r1[lane + 32 * c];
            acc0 = fmaf(v0.x, aff[c].x, acc0);
            acc0 = fmaf(v0.y, aff[c].y, acc0);
            acc0 = fmaf(v0.z, aff[c].z, acc0);
            acc0 = fmaf(v0.w, aff[c].w, acc0);
            acc1 = fmaf(v1.x, aff[c].x, acc1);
            acc1 = fmaf(v1.y, aff[c].y, acc1);
            acc1 = fmaf(v1.z, aff[c].z, acc1);
            acc1 = fmaf(v1.w, aff[c].w, acc1);
        }

        // warp reduction
        #pragma unroll
        for (int off = 16; off > 0; off >>= 1) {
            acc0 += __shfl_xor_sync(0xFFFFFFFFu, acc0, off);
            acc1 += __shfl_xor_sync(0xFFFFFFFFu, acc1, off);
        }

        if (lane == 0) {
            out[((size_t)b * S_ + (s0 + j))     * T_ + t] = acc0;
            out[((size_t)b * S_ + (s0 + j + 1)) * T_ + t] = acc1;
        }
    }
}

extern "C" void kernel_launch(void* const* d_in, const int* in_sizes, int n_in,
                              void* d_out, int out_size) {
    const float* in     = (const float*)d_in[0];
    const float* affine = (const float*)d_in[1];
    float* out          = (float*)d_out;
    (void)in_sizes; (void)n_in; (void)out_size;

    dim3 grid(B_ * T_ * 2);
    dim3 block(256);
    filtersum_kernel<<<grid, block>>>(in, affine, out);
}

// round 5
// speedup vs baseline: 1.1295x; 1.0649x over previous
#include <cuda_runtime.h>

// out[b,s,t] = sum_d input[b,t,s,d] * affine[d,t]
// B=8, T=128, S=256, D=1024, fp32.
// input : d_in[0], row (b,t,s,:) contiguous (4KB)
// affine: d_in[1], affine[d*T + t]
// out   : [B,S,T]

#define B_ 8
#define T_ 128
#define S_ 256
#define D_ 1024
#define D4 (D_ / 4)   // 256 float4 per row

__global__ __launch_bounds__(256)
void filtersum_kernel(const float* __restrict__ in,
                      const float* __restrict__ affine,
                      float* __restrict__ out) {
    __shared__ float aff_s[D_];

    const int bt = blockIdx.x;          // 0..B_*T_-1
    const int b  = bt / T_;
    const int t  = bt % T_;
    const int tid  = threadIdx.x;
    const int lane = tid & 31;
    const int w    = tid >> 5;          // warp id, 0..7

    // Cooperative load of affine column t into shared (strided gather, L2-hot).
    #pragma unroll
    for (int d = tid; d < D_; d += 256)
        aff_s[d] = affine[d * T_ + t];
    __syncthreads();

    // Per-lane affine chunks in registers: lane holds float4 at indices lane + 32*c.
    float4 aff[8];
    const float4* affs4 = reinterpret_cast<const float4*>(aff_s);
    #pragma unroll
    for (int c = 0; c < 8; c++)
        aff[c] = affs4[lane + 32 * c];

    const float4* base = reinterpret_cast<const float4*>(in)
                       + (size_t)(b * T_ + t) * S_ * D4;

    // Lockstep mapping: at iteration j, the 8 warps together cover rows
    // [j*16, j*16+16) — one contiguous 64KB window per block step, so the
    // block is a single sequential 1MB DRAM stream (vs 8 parallel stripes).
    #pragma unroll 1
    for (int j = 0; j < 16; j++) {
        const int s = j * 16 + w * 2;
        const float4* r0 = base + (size_t)s * D4;
        const float4* r1 = r0 + D4;

        float acc0 = 0.0f, acc1 = 0.0f;
        #pragma unroll
        for (int c = 0; c < 8; c++) {
            float4 v0 = r0[lane + 32 * c];
            float4 v1 = r1[lane + 32 * c];
            acc0 = fmaf(v0.x, aff[c].x, acc0);
            acc0 = fmaf(v0.y, aff[c].y, acc0);
            acc0 = fmaf(v0.z, aff[c].z, acc0);
            acc0 = fmaf(v0.w, aff[c].w, acc0);
            acc1 = fmaf(v1.x, aff[c].x, acc1);
            acc1 = fmaf(v1.y, aff[c].y, acc1);
            acc1 = fmaf(v1.z, aff[c].z, acc1);
            acc1 = fmaf(v1.w, aff[c].w, acc1);
        }

        // warp reduction
        #pragma unroll
        for (int off = 16; off > 0; off >>= 1) {
            acc0 += __shfl_xor_sync(0xFFFFFFFFu, acc0, off);
            acc1 += __shfl_xor_sync(0xFFFFFFFFu, acc1, off);
        }

        if (lane == 0) {
            out[((size_t)b * S_ + s)     * T_ + t] = acc0;
            out[((size_t)b * S_ + s + 1) * T_ + t] = acc1;
        }
    }
}

extern "C" void kernel_launch(void* const* d_in, const int* in_sizes, int n_in,
                              void* d_out, int out_size) {
    const float* in     = (const float*)d_in[0];
    const float* affine = (const float*)d_in[1];
    float* out          = (float*)d_out;
    (void)in_sizes; (void)n_in; (void)out_size;

    dim3 grid(B_ * T_);
    dim3 block(256);
    filtersum_kernel<<<grid, block>>>(in, affine, out);
}